// round 4
// baseline (speedup 1.0000x reference)
#include <cuda_runtime.h>
#include <cuda_bf16.h>
#include <cstdint>

#define SEQ   512
#define BAT   64
#define DH    1024
#define KP    3072                 // tri-split K' = 3*1024
#define MROWS (SEQ*BAT)            // 32768
#define BHD   (BAT*DH)             // 65536

#define GRID_REC 64
#define REC_THREADS 256
#define WPSZ  ((size_t)DH*KP)
#define LDT   72                   // padded smem row stride (bf16 elems)
#define NIT_REC 48                 // 3072/64
#define STAGES 3

// ---------------- device globals (no allocations allowed) -------------------
__device__ __nv_bfloat16 g_xp [(size_t)MROWS*KP];   // x tri-split (hi,lo,hi)
__device__ __nv_bfloat16 g_hsp[(size_t)MROWS*KP];   // hs tri-split
__device__ __nv_bfloat16 g_wp [7*WPSZ];             // weights tri-split (hi,hi,lo)
__device__ float g_xz[(size_t)SEQ*BHD];
__device__ float g_xr[(size_t)SEQ*BHD];
__device__ float g_xn[(size_t)SEQ*BHD];
__device__ float g_h [BHD];
__device__ float g_z [BHD];
__device__ __nv_bfloat16 g_hp [BAT*KP];             // h tri-split
__device__ __nv_bfloat16 g_rhp[BAT*KP];             // r*h tri-split
__device__ unsigned g_barcnt;
__device__ volatile unsigned g_barsense;

// ---------------- helpers ----------------------------------------------------
__device__ __forceinline__ void trisplit(float v, __nv_bfloat16& hi, __nv_bfloat16& lo) {
    hi = __float2bfloat16(v);
    lo = __float2bfloat16(v - __bfloat162float(hi));
}

__device__ __forceinline__ uint32_t smem_u32(const void* p) {
    return (uint32_t)__cvta_generic_to_shared(p);
}

__device__ __forceinline__ void ldsm_x4(uint32_t* r, uint32_t addr) {
    asm volatile("ldmatrix.sync.aligned.m8n8.x4.shared.b16 {%0,%1,%2,%3}, [%4];"
                 : "=r"(r[0]), "=r"(r[1]), "=r"(r[2]), "=r"(r[3]) : "r"(addr));
}

__device__ __forceinline__ void mma_bf16(float* d, const uint32_t* a,
                                         uint32_t b0, uint32_t b1) {
    asm volatile("mma.sync.aligned.m16n8k16.row.col.f32.bf16.bf16.f32 "
                 "{%0,%1,%2,%3},{%4,%5,%6,%7},{%8,%9},{%0,%1,%2,%3};"
                 : "+f"(d[0]), "+f"(d[1]), "+f"(d[2]), "+f"(d[3])
                 : "r"(a[0]), "r"(a[1]), "r"(a[2]), "r"(a[3]), "r"(b0), "r"(b1));
}

__device__ __forceinline__ void cp_async16(uint32_t saddr, const void* gptr) {
    asm volatile("cp.async.cg.shared.global [%0], [%1], 16;" :: "r"(saddr), "l"(gptr));
}
__device__ __forceinline__ void cp_commit() {
    asm volatile("cp.async.commit_group;");
}
template <int N>
__device__ __forceinline__ void cp_wait() {
    asm volatile("cp.async.wait_group %0;" :: "n"(N));
}

// ---------------- conversion kernels ----------------------------------------
__global__ void conv_a_kernel(const float* __restrict__ x) {
    size_t i = (size_t)blockIdx.x * 256 + threadIdx.x;   // < MROWS*DH
    float v = x[i];
    size_t m = i >> 10, k = i & 1023;
    __nv_bfloat16 hi, lo; trisplit(v, hi, lo);
    __nv_bfloat16* dst = g_xp + m * KP;
    dst[k] = hi; dst[1024 + k] = lo; dst[2048 + k] = hi;
}

__global__ void conv_w_kernel(const float* w0, const float* w1, const float* w2,
                              const float* w3, const float* w4, const float* w5,
                              const float* w6) {
    int z = blockIdx.z;
    const float* src = (z==0)?w0:(z==1)?w1:(z==2)?w2:(z==3)?w3:(z==4)?w4:(z==5)?w5:w6;
    size_t i = (size_t)blockIdx.x * 256 + threadIdx.x;   // < DH*DH
    float v = src[i];
    size_t row = i >> 10, k = i & 1023;
    __nv_bfloat16 hi, lo; trisplit(v, hi, lo);
    __nv_bfloat16* dst = g_wp + (size_t)z * WPSZ + row * KP;
    dst[k] = hi; dst[1024 + k] = hi; dst[2048 + k] = lo;
}

// ---------------- init -------------------------------------------------------
__global__ void init_h_kernel(const float* __restrict__ h0) {
    int i = blockIdx.x * 256 + threadIdx.x;
    float v = h0[i];
    g_h[i] = v;
    int b = i >> 10, k = i & 1023;
    __nv_bfloat16 hi, lo; trisplit(v, hi, lo);
    __nv_bfloat16* dst = g_hp + (size_t)b * KP;
    dst[k] = hi; dst[1024 + k] = lo; dst[2048 + k] = hi;
    if (i == 0) { g_barcnt = 0; g_barsense = 0; }
}

// ---------------- grid barrier ----------------------------------------------
__device__ __forceinline__ void gbar(unsigned& phase) {
    phase++;
    __threadfence();
    __syncthreads();
    if (threadIdx.x == 0) {
        unsigned a = atomicAdd(&g_barcnt, 1);
        if (a == GRID_REC - 1) {
            g_barcnt = 0;
            __threadfence();
            g_barsense = phase;
        } else {
            while (g_barsense != phase) { __nanosleep(32); }
        }
    }
    __syncthreads();
    __threadfence();
}

// ---------------- big bf16 GEMM: C[M,1024] = A'[M,KP] . W'[1024,KP]^T + bias -
// BM=128, BN=64, BK=64, 256 threads, 8 warps (4m x 2n), warp tile 32x32.
__global__ __launch_bounds__(256)
void gemm_bf16p(int a_sel, int w_base, int c_mode,
                const float* __restrict__ bias0, const float* __restrict__ bias1,
                const float* __restrict__ bias2, float* __restrict__ Cext) {
    const int z = blockIdx.z;
    const __nv_bfloat16* A = a_sel ? g_hsp : g_xp;
    const __nv_bfloat16* W = g_wp + (size_t)(w_base + z) * WPSZ;
    const float* bias = (z == 0) ? bias0 : (z == 1) ? bias1 : bias2;
    float* C = (c_mode == 1) ? Cext : (z == 0 ? g_xz : z == 1 ? g_xr : g_xn);

    __shared__ __nv_bfloat16 As[128 * LDT];
    __shared__ __nv_bfloat16 Bs[64 * LDT];

    const int m0 = blockIdx.y * 128, n0 = blockIdx.x * 64;
    const int t = threadIdx.x, lane = t & 31, w8 = t >> 5;
    const int wm = w8 >> 1, wn = w8 & 1;
    const int lr = t >> 3, lq = t & 7;

    float acc[2][4][4] = {};

    for (int k0 = 0; k0 < KP; k0 += 64) {
        #pragma unroll
        for (int p = 0; p < 4; ++p) {
            int r = lr + p * 32;
            ((uint4*)(As + r * LDT))[lq] =
                *((const uint4*)(A + (size_t)(m0 + r) * KP + k0) + lq);
        }
        #pragma unroll
        for (int p = 0; p < 2; ++p) {
            int r = lr + p * 32;
            ((uint4*)(Bs + r * LDT))[lq] =
                *((const uint4*)(W + (size_t)(n0 + r) * KP + k0) + lq);
        }
        __syncthreads();
        #pragma unroll
        for (int kk = 0; kk < 4; ++kk) {
            const int ks = kk * 16;
            uint32_t aF[2][4], bF[2][4];
            #pragma unroll
            for (int mi = 0; mi < 2; ++mi) {
                int arow = wm * 32 + mi * 16 + (lane & 15);
                int acol = ks + ((lane >> 4) << 3);
                ldsm_x4(aF[mi], smem_u32(As + arow * LDT + acol));
            }
            #pragma unroll
            for (int nq = 0; nq < 2; ++nq) {
                int brow = wn * 32 + nq * 16 + (lane & 7) + (((lane >> 4) & 1) << 3);
                int bcol = ks + (((lane >> 3) & 1) << 3);
                ldsm_x4(bF[nq], smem_u32(Bs + brow * LDT + bcol));
            }
            #pragma unroll
            for (int mi = 0; mi < 2; ++mi)
                #pragma unroll
                for (int nq = 0; nq < 2; ++nq) {
                    mma_bf16(acc[mi][2 * nq],     aF[mi], bF[nq][0], bF[nq][1]);
                    mma_bf16(acc[mi][2 * nq + 1], aF[mi], bF[nq][2], bF[nq][3]);
                }
        }
        __syncthreads();
    }

    #pragma unroll
    for (int mi = 0; mi < 2; ++mi)
        #pragma unroll
        for (int ni = 0; ni < 4; ++ni) {
            int row = m0 + wm * 32 + mi * 16 + (lane >> 2);
            int col = n0 + wn * 32 + ni * 8 + (lane & 3) * 2;
            float b0 = bias[col], b1 = bias[col + 1];
            float* a = acc[mi][ni];
            *(float2*)&C[(size_t)row * DH + col]       = make_float2(a[0] + b0, a[1] + b1);
            *(float2*)&C[(size_t)(row + 8) * DH + col] = make_float2(a[2] + b0, a[3] + b1);
        }
}

// ---------------- recurrence: pipelined 64x32 full-K tile --------------------
// 256 threads, 8 warps (4m x 2n), warp tile 16x16. acc[2][4] per thread.
// Ag: [64, KP] activations, Wg: weight rows n0..n0+31 (pre-offset), pitch KP.
__device__ __forceinline__ void mma_tile64x32(
    const __nv_bfloat16* __restrict__ Ag,
    const __nv_bfloat16* __restrict__ Wg,
    float acc[2][4],
    __nv_bfloat16 (*sA)[64 * LDT],
    __nv_bfloat16 (*sB)[32 * LDT]) {
    const int t = threadIdx.x, lane = t & 31, w8 = t >> 5;
    const int wm = w8 >> 1, wn = w8 & 1;
    const int lr = t >> 3, lq8 = (t & 7) * 8;       // row 0..31, col offset (bf16)

    // ---- stage loader: A rows lr & lr+32, B row lr ----
    auto load_stage = [&](int st, int kt) {
        const int k = kt * 64;
        cp_async16(smem_u32(&sA[st][lr * LDT + lq8]),
                   Ag + (size_t)lr * KP + k + lq8);
        cp_async16(smem_u32(&sA[st][(lr + 32) * LDT + lq8]),
                   Ag + (size_t)(lr + 32) * KP + k + lq8);
        cp_async16(smem_u32(&sB[st][lr * LDT + lq8]),
                   Wg + (size_t)lr * KP + k + lq8);
    };

    // prologue: issue STAGES-1 stages
    #pragma unroll
    for (int p = 0; p < STAGES - 1; ++p) {
        load_stage(p, p);
        cp_commit();
    }

    for (int kt = 0; kt < NIT_REC; ++kt) {
        cp_wait<STAGES - 2>();
        __syncthreads();
        const int st = kt % STAGES;
        #pragma unroll
        for (int kk = 0; kk < 4; ++kk) {
            const int ks = kk * 16;
            uint32_t aF[4], bF[4];
            int arow = wm * 16 + (lane & 15);
            int acol = ks + ((lane >> 4) << 3);
            ldsm_x4(aF, smem_u32(&sA[st][arow * LDT + acol]));
            int brow = wn * 16 + (lane & 7) + (((lane >> 4) & 1) << 3);
            int bcol = ks + (((lane >> 3) & 1) << 3);
            ldsm_x4(bF, smem_u32(&sB[st][brow * LDT + bcol]));
            mma_bf16(acc[0], aF, bF[0], bF[1]);
            mma_bf16(acc[1], aF, bF[2], bF[3]);
        }
        if (kt + STAGES - 1 < NIT_REC)
            load_stage((kt + STAGES - 1) % STAGES, kt + STAGES - 1);
        cp_commit();
    }
}

// ---------------- persistent recurrence -------------------------------------
// Phase ZR: 64 blocks = gate(2) x 32 n-tiles of 32, fused sigmoid epilogue.
// Phase N : 32 blocks = 32 n-tiles of 32, fused tanh + h update.
__global__ __launch_bounds__(REC_THREADS)
void recurrence_kernel() {
    __shared__ __nv_bfloat16 sA[STAGES][64 * LDT];
    __shared__ __nv_bfloat16 sB[STAGES][32 * LDT];

    const int bid = blockIdx.x;
    const int lane = threadIdx.x & 31, w8 = threadIdx.x >> 5;
    const int wm = w8 >> 1, wn = w8 & 1;
    unsigned phase = 0;

    const int gate = bid >> 5;                 // 0 = z, 1 = r
    const int n0zr = (bid & 31) * 32;
    const __nv_bfloat16* Wzr = g_wp + (size_t)(3 + gate) * WPSZ + (size_t)n0zr * KP;

    const int n0n = (bid & 31) * 32;
    const __nv_bfloat16* Wn = g_wp + (size_t)5 * WPSZ + (size_t)n0n * KP;

    const int r0 = wm * 16 + (lane >> 2);      // epilogue row base (batch)

    for (int s = 0; s < SEQ; ++s) {
        // ---------------- phase ZR ----------------
        {
            float acc[2][4] = {};
            mma_tile64x32(g_hp, Wzr, acc, sA, sB);
            const float* xg = (gate == 0) ? (g_xz + (size_t)s * BHD)
                                          : (g_xr + (size_t)s * BHD);
            #pragma unroll
            for (int ni = 0; ni < 2; ++ni) {
                int c = n0zr + wn * 16 + ni * 8 + (lane & 3) * 2;
                #pragma unroll
                for (int half = 0; half < 2; ++half) {
                    int row = r0 + half * 8;
                    #pragma unroll
                    for (int j = 0; j < 2; ++j) {
                        int col = c + j;
                        float a = acc[ni][half * 2 + j] + xg[row * DH + col];
                        float sg = 1.f / (1.f + __expf(-a));
                        if (gate == 0) {
                            g_z[row * DH + col] = sg;
                        } else {
                            float rh = sg * g_h[row * DH + col];
                            __nv_bfloat16 hi, lo; trisplit(rh, hi, lo);
                            __nv_bfloat16* dst = g_rhp + (size_t)row * KP + col;
                            dst[0] = hi; dst[1024] = lo; dst[2048] = hi;
                        }
                    }
                }
            }
        }
        gbar(phase);

        // ---------------- phase N ----------------
        if (bid < 32) {
            float acc[2][4] = {};
            mma_tile64x32(g_rhp, Wn, acc, sA, sB);
            const float* xg = g_xn + (size_t)s * BHD;
            #pragma unroll
            for (int ni = 0; ni < 2; ++ni) {
                int c = n0n + wn * 16 + ni * 8 + (lane & 3) * 2;
                #pragma unroll
                for (int half = 0; half < 2; ++half) {
                    int row = r0 + half * 8;
                    #pragma unroll
                    for (int j = 0; j < 2; ++j) {
                        int col = c + j;
                        float an = acc[ni][half * 2 + j] + xg[row * DH + col];
                        float nv = tanhf(an);
                        float zv = g_z[row * DH + col];
                        float h  = g_h[row * DH + col];
                        float hn = fmaf(zv, nv - h, h);
                        g_h[row * DH + col] = hn;
                        __nv_bfloat16 hi, lo; trisplit(hn, hi, lo);
                        __nv_bfloat16* dh = g_hp + (size_t)row * KP + col;
                        dh[0] = hi; dh[1024] = lo; dh[2048] = hi;
                        __nv_bfloat16* ds = g_hsp + ((size_t)s * BAT + row) * KP + col;
                        ds[0] = hi; ds[1024] = lo; ds[2048] = hi;
                    }
                }
            }
        }
        gbar(phase);
    }
}

__global__ void copy_hlast_kernel(float* __restrict__ dst) {
    int i = blockIdx.x * 256 + threadIdx.x;
    dst[i] = g_h[i];
}

// ---------------- launch ----------------------------------------------------
extern "C" void kernel_launch(void* const* d_in, const int* in_sizes, int n_in,
                              void* d_out, int out_size) {
    const float* x   = (const float*)d_in[0];
    const float* h0  = (const float*)d_in[1];
    const float* Wxz = (const float*)d_in[2];
    const float* bxz = (const float*)d_in[3];
    const float* Whz = (const float*)d_in[4];
    const float* Wxr = (const float*)d_in[5];
    const float* bxr = (const float*)d_in[6];
    const float* Whr = (const float*)d_in[7];
    const float* Wxn = (const float*)d_in[8];
    const float* bxn = (const float*)d_in[9];
    const float* Whn = (const float*)d_in[10];
    const float* Why = (const float*)d_in[11];
    const float* bhy = (const float*)d_in[12];
    float* out = (float*)d_out;

    // conversions: weights (order: Wxz,Wxr,Wxn,Whz,Whr,Whn,Why), then x
    conv_w_kernel<<<dim3(DH * DH / 256, 1, 7), 256>>>(Wxz, Wxr, Wxn, Whz, Whr, Whn, Why);
    conv_a_kernel<<<(size_t)MROWS * DH / 256, 256>>>(x);
    init_h_kernel<<<BHD / 256, 256>>>(h0);

    // pre-projections: xz, xr, xn in one launch (grid.z = gate)
    gemm_bf16p<<<dim3(DH / 64, MROWS / 128, 3), 256>>>(
        0, 0, 0, bxz, bxr, bxn, nullptr);

    // recurrence (persistent, 2 grid barriers per step)
    recurrence_kernel<<<GRID_REC, REC_THREADS>>>();

    // output GEMM: out = hs' . Why'^T + bhy
    gemm_bf16p<<<dim3(DH / 64, MROWS / 128, 1), 256>>>(
        1, 6, 1, bhy, bhy, bhy, out);

    copy_hlast_kernel<<<BHD / 256, 256>>>(out + (size_t)MROWS * DH);
}